// round 2
// baseline (speedup 1.0000x reference)
#include <cuda_runtime.h>

#define DINLINE __device__ __forceinline__

namespace {
constexpr int kTlen = 1024;
constexpr int kF = 64;
constexpr int kH = 256;
constexpr int kK = 320;          // K = H + F (vec = [h | x])
constexpr int kNJ = 16;          // hidden stripes per barrier group
constexpr int kBT = 16;          // batch rows per CTA
constexpr int kJT = 16;          // hidden cols per CTA (=> 64 gate cols)
constexpr int kNS = 16;          // k-slices (split-K)
constexpr int kKS = 20;          // k per slice
constexpr int kKP = 10;          // f32x2 pairs per slice
constexpr int kThreads = 256;
constexpr int kCtas = 128;       // 8 batch stripes x 16 hidden stripes
constexpr int kSmemBytes = 120 * 1024;  // force 1 CTA/SM => all CTAs resident
}

__device__ float g_h[2][128 * 256];
__device__ unsigned g_arrive[8];
__device__ unsigned g_epoch[8];

DINLINE unsigned long long pack2(float lo, float hi) {
  unsigned long long r;
  asm("mov.b64 %0, {%1, %2};" : "=l"(r) : "f"(lo), "f"(hi));
  return r;
}
DINLINE void ffma2(unsigned long long& d, unsigned long long a, unsigned long long b) {
  asm("fma.rn.f32x2 %0, %1, %2, %0;" : "+l"(d) : "l"(a), "l"(b));
}
DINLINE float2 unpack2(unsigned long long v) {
  float lo, hi;
  asm("mov.b64 {%0, %1}, %2;" : "=f"(lo), "=f"(hi) : "l"(v));
  return make_float2(lo, hi);
}
DINLINE float sigmoidf_(float x) { return __fdividef(1.0f, 1.0f + __expf(-x)); }

__global__ void __launch_bounds__(kThreads, 1)
lstm_seq2seq_kernel(const float* __restrict__ ts,
                    const float* __restrict__ Wih_e, const float* __restrict__ Whh_e,
                    const float* __restrict__ b_e,
                    const float* __restrict__ Wih_d, const float* __restrict__ Whh_d,
                    const float* __restrict__ b_d,
                    const float* __restrict__ Wout, const float* __restrict__ bout,
                    float* __restrict__ out) {
  extern __shared__ float smem[];
  float* vec = smem;                         // [16][320]  vec = [h_t | x_t]
  float* partial = smem + kBT * kK;          // [16 slices][16 b][64 c]
  float* wout_s = partial + kNS * kBT * 64;  // [4][256]
  float* bout_s = wout_s + 4 * kH;           // [4]

  const int tid = threadIdx.x;
  const int jstripe = blockIdx.x & (kNJ - 1);
  const int bstripe = blockIdx.x >> 4;
  const int grp = bstripe;

  const int slice = tid >> 4;   // 0..15  (k-slice, GEMM phase)
  const int cg = tid & 15;      // 0..15  (gate-col group of 4)
  const int bl = tid >> 4;      // update phase: local batch row
  const int jj = tid & 15;      // update phase: local hidden col

  unsigned ebase = 0;
  if (tid == 0) ebase = g_epoch[grp];
  unsigned barno = 0;

  // init h0 = 0 for owned (b,j); stage W_out tile + b_out
  g_h[0][(bstripe * kBT + bl) * kH + jstripe * kJT + jj] = 0.0f;
  for (int idx = tid; idx < 4 * kH; idx += kThreads)
    wout_s[idx] = Wout[jstripe * 4 * kH + idx];
  if (tid < 4) bout_s[tid] = bout[jstripe * 4 + tid];

  unsigned long long w2[4][kKP];  // register-resident weights (f32x2 k-pairs)
  float bias[4];
  float cst = 0.0f;               // cell state, register-resident across ALL steps

  auto load_w = [&](const float* Wih, const float* Whh, const float* bv) {
#pragma unroll
    for (int cc = 0; cc < 4; ++cc) {
      const int c = cg * 4 + cc;  // gate col 0..63 = gate*16 + j
      const int row = (c >> 4) * kH + jstripe * kJT + (c & 15);
#pragma unroll
      for (int kp = 0; kp < kKP; ++kp) {
        const int k0 = slice * kKS + 2 * kp;
        float a, b;
        if (k0 < kH) { a = Whh[row * kH + k0];        b = Whh[row * kH + k0 + 1]; }
        else         { a = Wih[row * kF + (k0 - kH)]; b = Wih[row * kF + (k0 - kH) + 1]; }
        w2[cc][kp] = pack2(a, b);
      }
    }
    const int jg = jstripe * kJT + jj;
#pragma unroll
    for (int g = 0; g < 4; ++g) bias[g] = bv[g * kH + jg];
  };

  // 16-CTA group barrier. Epoch targets are RELATIVE to the value at kernel
  // entry and g_arrive returns to 0 after each barrier -> graph-replay safe.
  auto gbar = [&]() {
    __syncthreads();
    if (tid == 0) {
      ++barno;
      __threadfence();
      const unsigned prev = atomicAdd(&g_arrive[grp], 1u);
      const unsigned target = ebase + barno;
      if (prev == kNJ - 1) {
        atomicExch(&g_arrive[grp], 0u);
        __threadfence();
        atomicExch(&g_epoch[grp], target);
      } else {
        volatile unsigned* ep = &g_epoch[grp];
        while (*ep != target) { }
      }
      __threadfence();
    }
    __syncthreads();
  };

  auto step = [&](int t, int buf, bool dec) {
    gbar();

    // ---- stage vec = [h_t | x_t] into smem (coalesced) ----
    const float* hb = g_h[buf] + bstripe * kBT * kH;
    {
      const int r0 = tid >> 6, kc = tid & 63;
#pragma unroll
      for (int p = 0; p < 4; ++p) {
        const int row = p * 4 + r0;
        float4 v = reinterpret_cast<const float4*>(hb + row * kH)[kc];
        reinterpret_cast<float4*>(vec + row * kK)[kc] = v;
      }
      const int row = tid >> 4, kx = tid & 15;
      float4 vx = reinterpret_cast<const float4*>(
          ts + (((bstripe * kBT + row) * kTlen + t) * kF))[kx];
      reinterpret_cast<float4*>(vec + row * kK + kH)[kx] = vx;
    }
    __syncthreads();

    if (dec) {
      // out_t = h_pre @ Wout^T + bout  (4-way split-K + shuffle reduce)
      const int o = tid >> 2, p = tid & 3;
      const int ob = o >> 2, ofi = o & 3;
      const float4* v4 = reinterpret_cast<const float4*>(vec + ob * kK + p * 64);
      const float4* w4 = reinterpret_cast<const float4*>(wout_s + ofi * kH + p * 64);
      float s = 0.0f;
#pragma unroll
      for (int i = 0; i < 16; ++i) {
        const float4 a = v4[i], b = w4[i];
        s += a.x * b.x + a.y * b.y + a.z * b.z + a.w * b.w;
      }
      s += __shfl_xor_sync(0xffffffffu, s, 1);
      s += __shfl_xor_sync(0xffffffffu, s, 2);
      if (p == 0)
        out[((bstripe * kBT + ob) * kTlen + t) * kF + jstripe * 4 + ofi] =
            s + bout_s[ofi];
    }

    // ---- gate GEMM partials: f32x2 FMAs, weights in registers ----
    const unsigned long long* vec2 = reinterpret_cast<const unsigned long long*>(vec);
#pragma unroll
    for (int bg = 0; bg < 4; ++bg) {
      unsigned long long acc[4][4];
#pragma unroll
      for (int bb = 0; bb < 4; ++bb)
#pragma unroll
        for (int cc = 0; cc < 4; ++cc) acc[bb][cc] = 0ull;
#pragma unroll
      for (int kp = 0; kp < kKP; ++kp) {
#pragma unroll
        for (int bb = 0; bb < 4; ++bb) {
          const unsigned long long v =
              vec2[(bg * 4 + bb) * (kK / 2) + slice * (kKS / 2) + kp];
#pragma unroll
          for (int cc = 0; cc < 4; ++cc) ffma2(acc[bb][cc], v, w2[cc][kp]);
        }
      }
#pragma unroll
      for (int bb = 0; bb < 4; ++bb) {
        const float2 f0 = unpack2(acc[bb][0]);
        const float2 f1 = unpack2(acc[bb][1]);
        const float2 f2 = unpack2(acc[bb][2]);
        const float2 f3 = unpack2(acc[bb][3]);
        float4 r = make_float4(f0.x + f0.y, f1.x + f1.y, f2.x + f2.y, f3.x + f3.y);
        reinterpret_cast<float4*>(
            partial + (slice * kBT + bg * 4 + bb) * 64 + cg * 4)[0] = r;
      }
    }
    __syncthreads();

    // ---- reduce 16 slices + LSTM cell update (c stays in register) ----
    {
      float gv[4];
#pragma unroll
      for (int g = 0; g < 4; ++g) {
        const float* pp = partial + bl * 64 + g * 16 + jj;
        float s = 0.0f;
#pragma unroll
        for (int sl = 0; sl < kNS; ++sl) s += pp[sl * kBT * 64];
        gv[g] = s + bias[g];
      }
      const float ig = sigmoidf_(gv[0]);
      const float fg = sigmoidf_(gv[1]);
      const float gg = tanhf(gv[2]);
      const float og = sigmoidf_(gv[3]);
      cst = fg * cst + ig * gg;
      const float hv = og * tanhf(cst);
      g_h[buf ^ 1][(bstripe * kBT + bl) * kH + jstripe * kJT + jj] = hv;
    }
  };

  // ---- encoder: t ascending ----
  load_w(Wih_e, Whh_e, b_e);
  for (int t = 0; t < kTlen; ++t) step(t, t & 1, false);

  // ---- decoder: t descending, emit projection of pre-update h ----
  load_w(Wih_d, Whh_d, b_d);
  for (int i = 0; i < kTlen; ++i) step(kTlen - 1 - i, i & 1, true);
}

extern "C" void kernel_launch(void* const* d_in, const int* in_sizes, int n_in,
                              void* d_out, int out_size) {
  cudaFuncSetAttribute(lstm_seq2seq_kernel,
                       cudaFuncAttributeMaxDynamicSharedMemorySize, kSmemBytes);
  lstm_seq2seq_kernel<<<kCtas, kThreads, kSmemBytes>>>(
      (const float*)d_in[0], (const float*)d_in[1], (const float*)d_in[2],
      (const float*)d_in[3], (const float*)d_in[4], (const float*)d_in[5],
      (const float*)d_in[6], (const float*)d_in[7], (const float*)d_in[8],
      (float*)d_out);
}